// round 2
// baseline (speedup 1.0000x reference)
#include <cuda_runtime.h>

// VAE forward, B = 4,000,000 rows. R=4 rows per thread so each shared-weight
// load (LDS broadcast) is reused by 4 FMAs: LDS/row drops 168 -> 42, removing
// the L1 bottleneck seen in round 1 (L1=76% > DRAM=65%).
//
// Inputs: x[B,8], eps[B,4], w1[6,8], w21[4,6], w22[4,6], w3[6,4], w4[8,6]
// Output: concat(out[B,8], mu[B,4], logvar[B,4]) float32.

#define NTHREADS 256
#define R 4

__device__ __forceinline__ float elu_f(float v) {
    return v > 0.0f ? v : (__expf(v) - 1.0f);
}

__global__ __launch_bounds__(NTHREADS)
void vae_kernel(const float4* __restrict__ x,    // B*2 float4
                const float4* __restrict__ eps,  // B   float4
                const float*  __restrict__ w1,   // 48
                const float*  __restrict__ w21,  // 24
                const float*  __restrict__ w22,  // 24
                const float*  __restrict__ w3,   // 24
                const float*  __restrict__ w4,   // 48
                float4* __restrict__ out,        // B*2 float4
                float4* __restrict__ mu_out,     // B   float4
                float4* __restrict__ lv_out,     // B   float4
                int B)
{
    __shared__ float sw1[48], sw21[24], sw22[24], sw3[24], sw4[48];
    const int t = threadIdx.x;
    if (t < 48) sw1[t] = w1[t];
    if (t < 24) { sw21[t] = w21[t]; sw22[t] = w22[t]; sw3[t] = w3[t]; }
    if (t < 48) sw4[t] = w4[t];
    __syncthreads();

    const int base = blockIdx.x * (NTHREADS * R) + t;

    // ---- phase 1: issue all global loads up front (12 LDG.128 in flight) ----
    float xv[R][8];
    float ev[R][4];
#pragma unroll
    for (int r = 0; r < R; r++) {
        const int row = base + r * NTHREADS;
        if (row < B) {
            const float4 a = x[2 * row];
            const float4 b = x[2 * row + 1];
            xv[r][0] = a.x; xv[r][1] = a.y; xv[r][2] = a.z; xv[r][3] = a.w;
            xv[r][4] = b.x; xv[r][5] = b.y; xv[r][6] = b.z; xv[r][7] = b.w;
            const float4 e = eps[row];
            ev[r][0] = e.x; ev[r][1] = e.y; ev[r][2] = e.z; ev[r][3] = e.w;
        } else {
#pragma unroll
            for (int k = 0; k < 8; k++) xv[r][k] = 0.0f;
#pragma unroll
            for (int k = 0; k < 4; k++) ev[r][k] = 0.0f;
        }
    }

    // ---- encoder: h1 = elu(x @ w1.T); neuron-outer so weights load once ----
    float h1[R][6];
#pragma unroll
    for (int j = 0; j < 6; j++) {
        float w[8];
#pragma unroll
        for (int k = 0; k < 8; k++) w[k] = sw1[j * 8 + k];
#pragma unroll
        for (int r = 0; r < R; r++) {
            float s = 0.0f;
#pragma unroll
            for (int k = 0; k < 8; k++) s = fmaf(xv[r][k], w[k], s);
            h1[r][j] = elu_f(s);
        }
    }

    // ---- mu = h1 @ w21.T, logvar = h1 @ w22.T ----
    float mu[R][4], lv[R][4];
#pragma unroll
    for (int j = 0; j < 4; j++) {
        float wm[6], wl[6];
#pragma unroll
        for (int k = 0; k < 6; k++) { wm[k] = sw21[j * 6 + k]; wl[k] = sw22[j * 6 + k]; }
#pragma unroll
        for (int r = 0; r < R; r++) {
            float sm = 0.0f, sl = 0.0f;
#pragma unroll
            for (int k = 0; k < 6; k++) {
                sm = fmaf(h1[r][k], wm[k], sm);
                sl = fmaf(h1[r][k], wl[k], sl);
            }
            mu[r][j] = sm;
            lv[r][j] = sl;
        }
    }

    // ---- store mu/logvar, reparameterize z = mu + eps * exp(0.5*lv) ----
    float z[R][4];
#pragma unroll
    for (int r = 0; r < R; r++) {
        const int row = base + r * NTHREADS;
        if (row < B) {
            mu_out[row] = make_float4(mu[r][0], mu[r][1], mu[r][2], mu[r][3]);
            lv_out[row] = make_float4(lv[r][0], lv[r][1], lv[r][2], lv[r][3]);
        }
#pragma unroll
        for (int j = 0; j < 4; j++)
            z[r][j] = fmaf(ev[r][j], __expf(0.5f * lv[r][j]), mu[r][j]);
    }

    // ---- decoder: h3 = elu(z @ w3.T) ----
    float h3[R][6];
#pragma unroll
    for (int j = 0; j < 6; j++) {
        float w[4];
#pragma unroll
        for (int k = 0; k < 4; k++) w[k] = sw3[j * 4 + k];
#pragma unroll
        for (int r = 0; r < R; r++) {
            float s = 0.0f;
#pragma unroll
            for (int k = 0; k < 4; k++) s = fmaf(z[r][k], w[k], s);
            h3[r][j] = elu_f(s);
        }
    }

    // ---- out = h3 @ w4.T ----
    float o[R][8];
#pragma unroll
    for (int j = 0; j < 8; j++) {
        float w[6];
#pragma unroll
        for (int k = 0; k < 6; k++) w[k] = sw4[j * 6 + k];
#pragma unroll
        for (int r = 0; r < R; r++) {
            float s = 0.0f;
#pragma unroll
            for (int k = 0; k < 6; k++) s = fmaf(h3[r][k], w[k], s);
            o[r][j] = s;
        }
    }

#pragma unroll
    for (int r = 0; r < R; r++) {
        const int row = base + r * NTHREADS;
        if (row < B) {
            out[2 * row]     = make_float4(o[r][0], o[r][1], o[r][2], o[r][3]);
            out[2 * row + 1] = make_float4(o[r][4], o[r][5], o[r][6], o[r][7]);
        }
    }
}

extern "C" void kernel_launch(void* const* d_in, const int* in_sizes, int n_in,
                              void* d_out, int out_size)
{
    const float4* x   = (const float4*)d_in[0];
    const float4* eps = (const float4*)d_in[1];
    const float*  w1  = (const float*)d_in[2];
    const float*  w21 = (const float*)d_in[3];
    const float*  w22 = (const float*)d_in[4];
    const float*  w3  = (const float*)d_in[5];
    const float*  w4  = (const float*)d_in[6];

    const int B = in_sizes[0] / 8;

    float* outf = (float*)d_out;
    float4* out    = (float4*)outf;
    float4* mu_out = (float4*)(outf + (size_t)B * 8);
    float4* lv_out = (float4*)(outf + (size_t)B * 12);

    const int rows_per_block = NTHREADS * R;
    const int grid = (B + rows_per_block - 1) / rows_per_block;
    vae_kernel<<<grid, NTHREADS>>>(x, eps, w1, w21, w22, w3, w4,
                                   out, mu_out, lv_out, B);
}

// round 3
// speedup vs baseline: 1.1142x; 1.1142x over previous
#include <cuda_runtime.h>

// VAE forward, B = 4,000,000 rows.
// R1 lesson: scalar LDS weight loads bound L1 (76%). R2 lesson: R=4 rows/thread
// killed occupancy (95 regs -> 22%). This round: R=1 (keeps occ ~60%) but all
// weight loads are float4 LDS.128 broadcasts from padded shared arrays:
// 168 scalar LDS/row -> 50 LDS.128/row (~3x fewer L1 wavefronts).
//
// Inputs: x[B,8], eps[B,4], w1[6,8], w21[4,6], w22[4,6], w3[6,4], w4[8,6]
// Output: concat(out[B,8], mu[B,4], logvar[B,4]) float32.

#define NTHREADS 256

__device__ __forceinline__ float elu_f(float v) {
    return v > 0.0f ? v : (__expf(v) - 1.0f);
}

__device__ __forceinline__ float dot4(float4 a, float4 b) {
    float s = a.x * b.x;
    s = fmaf(a.y, b.y, s);
    s = fmaf(a.z, b.z, s);
    s = fmaf(a.w, b.w, s);
    return s;
}

__global__ __launch_bounds__(NTHREADS)
void vae_kernel(const float4* __restrict__ x,    // B*2 float4
                const float4* __restrict__ eps,  // B   float4
                const float*  __restrict__ w1,   // 48  [6,8]
                const float*  __restrict__ w21,  // 24  [4,6]
                const float*  __restrict__ w22,  // 24  [4,6]
                const float*  __restrict__ w3,   // 24  [6,4]
                const float*  __restrict__ w4,   // 48  [8,6]
                float4* __restrict__ out,        // B*2 float4
                float4* __restrict__ mu_out,     // B   float4
                float4* __restrict__ lv_out,     // B   float4
                int B)
{
    // Padded float4 weight banks:
    //  sw1 : 6 rows x 2 f4 (8 floats/row, exact)
    //  sw21: 4 rows x 2 f4 (6 floats + 2 pad)
    //  sw22: 4 rows x 2 f4
    //  sw3 : 6 rows x 1 f4 (4 floats/row, exact)
    //  sw4 : 8 rows x 2 f4 (6 floats + 2 pad)
    __shared__ float4 sw1[12], sw21[8], sw22[8], sw3[6], sw4[16];

    const int t = threadIdx.x;
    // zero the padded banks (covers pad lanes), then scatter weights
    {
        float* s21 = (float*)sw21;
        float* s22 = (float*)sw22;
        float* s4  = (float*)sw4;
        if (t < 32) { s21[t] = 0.0f; s22[t] = 0.0f; }
        if (t < 64) { s4[t] = 0.0f; }
        __syncthreads();
        float* s1 = (float*)sw1;
        float* s3 = (float*)sw3;
        if (t < 48) s1[t] = w1[t];                       // exact layout
        if (t < 24) {
            const int r = t / 6, c = t % 6;
            s21[r * 8 + c] = w21[t];
            s22[r * 8 + c] = w22[t];
            s3[t] = w3[t];                               // exact layout [6,4]
        }
        if (t < 48) {
            const int r = t / 6, c = t % 6;
            s4[r * 8 + c] = w4[t];
        }
        __syncthreads();
    }

    const int i = blockIdx.x * NTHREADS + t;
    if (i >= B) return;

    const float4 xa = x[2 * i];
    const float4 xb = x[2 * i + 1];
    const float4 e  = eps[i];

    // ---- encoder: h1 = elu(x @ w1.T) ----
    float h1a4x, h1a4y, h1a4z, h1a4w;  // h1[0..3]
    float h1_4, h1_5;
    float h1[6];
#pragma unroll
    for (int j = 0; j < 6; j++) {
        const float4 wa = sw1[2 * j];
        const float4 wb = sw1[2 * j + 1];
        h1[j] = elu_f(dot4(xa, wa) + dot4(xb, wb));
    }
    const float4 h1a = make_float4(h1[0], h1[1], h1[2], h1[3]);
    (void)h1a4x; (void)h1a4y; (void)h1a4z; (void)h1a4w; (void)h1_4; (void)h1_5;

    // ---- mu / logvar: [4,6] padded to 8 ----
    float mu[4], lv[4];
#pragma unroll
    for (int j = 0; j < 4; j++) {
        const float4 ma = sw21[2 * j];
        const float4 mb = sw21[2 * j + 1];
        const float4 la = sw22[2 * j];
        const float4 lb = sw22[2 * j + 1];
        float sm = dot4(h1a, ma);
        sm = fmaf(h1[4], mb.x, sm);
        sm = fmaf(h1[5], mb.y, sm);
        float sl = dot4(h1a, la);
        sl = fmaf(h1[4], lb.x, sl);
        sl = fmaf(h1[5], lb.y, sl);
        mu[j] = sm;
        lv[j] = sl;
    }

    mu_out[i] = make_float4(mu[0], mu[1], mu[2], mu[3]);
    lv_out[i] = make_float4(lv[0], lv[1], lv[2], lv[3]);

    // ---- reparameterize ----
    const float4 zv = make_float4(
        fmaf(e.x, __expf(0.5f * lv[0]), mu[0]),
        fmaf(e.y, __expf(0.5f * lv[1]), mu[1]),
        fmaf(e.z, __expf(0.5f * lv[2]), mu[2]),
        fmaf(e.w, __expf(0.5f * lv[3]), mu[3]));

    // ---- decoder: h3 = elu(z @ w3.T), w3 row = 1 float4 ----
    float h3[6];
#pragma unroll
    for (int j = 0; j < 6; j++)
        h3[j] = elu_f(dot4(zv, sw3[j]));
    const float4 h3a = make_float4(h3[0], h3[1], h3[2], h3[3]);

    // ---- out = h3 @ w4.T, [8,6] padded to 8 ----
    float o[8];
#pragma unroll
    for (int j = 0; j < 8; j++) {
        const float4 wa = sw4[2 * j];
        const float4 wb = sw4[2 * j + 1];
        float s = dot4(h3a, wa);
        s = fmaf(h3[4], wb.x, s);
        s = fmaf(h3[5], wb.y, s);
        o[j] = s;
    }

    out[2 * i]     = make_float4(o[0], o[1], o[2], o[3]);
    out[2 * i + 1] = make_float4(o[4], o[5], o[6], o[7]);
}

extern "C" void kernel_launch(void* const* d_in, const int* in_sizes, int n_in,
                              void* d_out, int out_size)
{
    const float4* x   = (const float4*)d_in[0];
    const float4* eps = (const float4*)d_in[1];
    const float*  w1  = (const float*)d_in[2];
    const float*  w21 = (const float*)d_in[3];
    const float*  w22 = (const float*)d_in[4];
    const float*  w3  = (const float*)d_in[5];
    const float*  w4  = (const float*)d_in[6];

    const int B = in_sizes[0] / 8;

    float* outf = (float*)d_out;
    float4* out    = (float4*)outf;
    float4* mu_out = (float4*)(outf + (size_t)B * 8);
    float4* lv_out = (float4*)(outf + (size_t)B * 12);

    const int grid = (B + NTHREADS - 1) / NTHREADS;
    vae_kernel<<<grid, NTHREADS>>>(x, eps, w1, w21, w22, w3, w4,
                                   out, mu_out, lv_out, B);
}

// round 4
// speedup vs baseline: 1.2284x; 1.1025x over previous
#include <cuda_runtime.h>

// VAE forward, B = 4,000,000 rows, 2 rows per thread packed into f32x2 lanes.
// fma.rn.f32x2 (sm_103a packed fp32) halves FMA instruction count; weights are
// duplicated (w,w) in shared so one LDS.128 feeds two packed weights.
// Per-row: 84 FFMA2 + 42 LDS.128 + scalar ELU/exp, vs ~390 instrs in round 1.
//
// Inputs: x[B,8], eps[B,4], w1[6,8], w21[4,6], w22[4,6], w3[6,4], w4[8,6]
// Output: concat(out[B,8], mu[B,4], logvar[B,4]) float32.

#define NT 256

typedef unsigned long long u64;

__device__ __forceinline__ u64 pk(float lo, float hi) {
    u64 d; asm("mov.b64 %0,{%1,%2};" : "=l"(d) : "f"(lo), "f"(hi)); return d;
}
__device__ __forceinline__ void upk(float& lo, float& hi, u64 v) {
    asm("mov.b64 {%0,%1},%2;" : "=f"(lo), "=f"(hi) : "l"(v));
}
__device__ __forceinline__ u64 fma2(u64 a, u64 b, u64 c) {
    u64 d; asm("fma.rn.f32x2 %0,%1,%2,%3;" : "=l"(d) : "l"(a), "l"(b), "l"(c)); return d;
}
__device__ __forceinline__ u64 mul2(u64 a, u64 b) {
    u64 d; asm("mul.rn.f32x2 %0,%1,%2;" : "=l"(d) : "l"(a), "l"(b)); return d;
}
__device__ __forceinline__ u64 elu2(u64 s) {
    float lo, hi; upk(lo, hi, s);
    lo = lo > 0.0f ? lo : (__expf(lo) - 1.0f);
    hi = hi > 0.0f ? hi : (__expf(hi) - 1.0f);
    return pk(lo, hi);
}

// Shared duplicated-weight bank: 168 weight-pairs (8B each) = 1344B.
// Pair index layout: W1 [0,48) j*8+k | W21 [48,72) j*6+k | W22 [72,96)
//                    W3 [96,120) j*4+k | W4 [120,168) j*6+k
// ulonglong2 index = pair/2; every matrix row starts at an even pair.

__global__ __launch_bounds__(NT)
void vae_kernel(const float4* __restrict__ x,
                const float4* __restrict__ eps,
                const float*  __restrict__ w1,
                const float*  __restrict__ w21,
                const float*  __restrict__ w22,
                const float*  __restrict__ w3,
                const float*  __restrict__ w4,
                float4* __restrict__ out,
                float4* __restrict__ mu_out,
                float4* __restrict__ lv_out,
                int B)
{
    __shared__ ulonglong2 sd[84];
    {
        float* sf = (float*)sd;
        const int t = threadIdx.x;
        if (t < 48) { sf[2 * t] = w1[t];            sf[2 * t + 1] = sf[2 * t]; }
        if (t < 24) {
            sf[2 * (48 + t)] = w21[t];  sf[2 * (48 + t) + 1] = sf[2 * (48 + t)];
            sf[2 * (72 + t)] = w22[t];  sf[2 * (72 + t) + 1] = sf[2 * (72 + t)];
            sf[2 * (96 + t)] = w3[t];   sf[2 * (96 + t) + 1] = sf[2 * (96 + t)];
        }
        if (t < 48) { sf[2 * (120 + t)] = w4[t];    sf[2 * (120 + t) + 1] = sf[2 * (120 + t)]; }
        __syncthreads();
    }

    const int t  = threadIdx.x;
    const int i0 = blockIdx.x * (2 * NT) + t;
    const int i1 = i0 + NT;
    const bool v0 = i0 < B;
    const bool v1 = i1 < B;
    if (!v0) return;

    const float4 z4 = make_float4(0.f, 0.f, 0.f, 0.f);

    // ---- 6 front-batched LDG.128 ----
    const float4 xa0 = __ldcs(&x[2 * i0]);
    const float4 xb0 = __ldcs(&x[2 * i0 + 1]);
    const float4 e0  = __ldcs(&eps[i0]);
    const float4 xa1 = v1 ? __ldcs(&x[2 * i1])     : z4;
    const float4 xb1 = v1 ? __ldcs(&x[2 * i1 + 1]) : z4;
    const float4 e1  = v1 ? __ldcs(&eps[i1])       : z4;

    u64 X[8];
    X[0] = pk(xa0.x, xa1.x); X[1] = pk(xa0.y, xa1.y);
    X[2] = pk(xa0.z, xa1.z); X[3] = pk(xa0.w, xa1.w);
    X[4] = pk(xb0.x, xb1.x); X[5] = pk(xb0.y, xb1.y);
    X[6] = pk(xb0.z, xb1.z); X[7] = pk(xb0.w, xb1.w);
    u64 E[4];
    E[0] = pk(e0.x, e1.x); E[1] = pk(e0.y, e1.y);
    E[2] = pk(e0.z, e1.z); E[3] = pk(e0.w, e1.w);

    // ---- encoder: h1 = elu(x @ w1.T); row j = 4 LDS.128 ----
    u64 h1[6];
#pragma unroll
    for (int j = 0; j < 6; j++) {
        const ulonglong2 p0 = sd[j * 4 + 0];
        const ulonglong2 p1 = sd[j * 4 + 1];
        const ulonglong2 p2 = sd[j * 4 + 2];
        const ulonglong2 p3 = sd[j * 4 + 3];
        u64 s = mul2(X[0], p0.x);
        s = fma2(X[1], p0.y, s);
        s = fma2(X[2], p1.x, s);
        s = fma2(X[3], p1.y, s);
        s = fma2(X[4], p2.x, s);
        s = fma2(X[5], p2.y, s);
        s = fma2(X[6], p3.x, s);
        s = fma2(X[7], p3.y, s);
        h1[j] = elu2(s);
    }

    // ---- mu / logvar: rows of 6 pairs = 3 LDS.128 each ----
    u64 mu[4], lv[4];
#pragma unroll
    for (int j = 0; j < 4; j++) {
        const ulonglong2 m0 = sd[24 + j * 3 + 0];
        const ulonglong2 m1 = sd[24 + j * 3 + 1];
        const ulonglong2 m2 = sd[24 + j * 3 + 2];
        u64 sm = mul2(h1[0], m0.x);
        sm = fma2(h1[1], m0.y, sm);
        sm = fma2(h1[2], m1.x, sm);
        sm = fma2(h1[3], m1.y, sm);
        sm = fma2(h1[4], m2.x, sm);
        sm = fma2(h1[5], m2.y, sm);
        mu[j] = sm;
        const ulonglong2 l0 = sd[36 + j * 3 + 0];
        const ulonglong2 l1 = sd[36 + j * 3 + 1];
        const ulonglong2 l2 = sd[36 + j * 3 + 2];
        u64 sl = mul2(h1[0], l0.x);
        sl = fma2(h1[1], l0.y, sl);
        sl = fma2(h1[2], l1.x, sl);
        sl = fma2(h1[3], l1.y, sl);
        sl = fma2(h1[4], l2.x, sl);
        sl = fma2(h1[5], l2.y, sl);
        lv[j] = sl;
    }

    // ---- unpack mu/lv, store, reparameterize ----
    float m0a, m0b, m1a, m1b, m2a, m2b, m3a, m3b;
    upk(m0a, m0b, mu[0]); upk(m1a, m1b, mu[1]);
    upk(m2a, m2b, mu[2]); upk(m3a, m3b, mu[3]);
    float l0a, l0b, l1a, l1b, l2a, l2b, l3a, l3b;
    upk(l0a, l0b, lv[0]); upk(l1a, l1b, lv[1]);
    upk(l2a, l2b, lv[2]); upk(l3a, l3b, lv[3]);

    __stcs(&mu_out[i0], make_float4(m0a, m1a, m2a, m3a));
    __stcs(&lv_out[i0], make_float4(l0a, l1a, l2a, l3a));
    if (v1) {
        __stcs(&mu_out[i1], make_float4(m0b, m1b, m2b, m3b));
        __stcs(&lv_out[i1], make_float4(l0b, l1b, l2b, l3b));
    }

    u64 z[4];
    z[0] = fma2(E[0], pk(__expf(0.5f * l0a), __expf(0.5f * l0b)), mu[0]);
    z[1] = fma2(E[1], pk(__expf(0.5f * l1a), __expf(0.5f * l1b)), mu[1]);
    z[2] = fma2(E[2], pk(__expf(0.5f * l2a), __expf(0.5f * l2b)), mu[2]);
    z[3] = fma2(E[3], pk(__expf(0.5f * l3a), __expf(0.5f * l3b)), mu[3]);

    // ---- decoder: h3 = elu(z @ w3.T); rows of 4 pairs = 2 LDS.128 ----
    u64 h3[6];
#pragma unroll
    for (int j = 0; j < 6; j++) {
        const ulonglong2 p0 = sd[48 + j * 2 + 0];
        const ulonglong2 p1 = sd[48 + j * 2 + 1];
        u64 s = mul2(z[0], p0.x);
        s = fma2(z[1], p0.y, s);
        s = fma2(z[2], p1.x, s);
        s = fma2(z[3], p1.y, s);
        h3[j] = elu2(s);
    }

    // ---- out = h3 @ w4.T; rows of 6 pairs = 3 LDS.128 ----
    float oa[8], ob[8];
#pragma unroll
    for (int j = 0; j < 8; j++) {
        const ulonglong2 p0 = sd[60 + j * 3 + 0];
        const ulonglong2 p1 = sd[60 + j * 3 + 1];
        const ulonglong2 p2 = sd[60 + j * 3 + 2];
        u64 s = mul2(h3[0], p0.x);
        s = fma2(h3[1], p0.y, s);
        s = fma2(h3[2], p1.x, s);
        s = fma2(h3[3], p1.y, s);
        s = fma2(h3[4], p2.x, s);
        s = fma2(h3[5], p2.y, s);
        upk(oa[j], ob[j], s);
    }

    __stcs(&out[2 * i0],     make_float4(oa[0], oa[1], oa[2], oa[3]));
    __stcs(&out[2 * i0 + 1], make_float4(oa[4], oa[5], oa[6], oa[7]));
    if (v1) {
        __stcs(&out[2 * i1],     make_float4(ob[0], ob[1], ob[2], ob[3]));
        __stcs(&out[2 * i1 + 1], make_float4(ob[4], ob[5], ob[6], ob[7]));
    }
}

extern "C" void kernel_launch(void* const* d_in, const int* in_sizes, int n_in,
                              void* d_out, int out_size)
{
    const float4* x   = (const float4*)d_in[0];
    const float4* eps = (const float4*)d_in[1];
    const float*  w1  = (const float*)d_in[2];
    const float*  w21 = (const float*)d_in[3];
    const float*  w22 = (const float*)d_in[4];
    const float*  w3  = (const float*)d_in[5];
    const float*  w4  = (const float*)d_in[6];

    const int B = in_sizes[0] / 8;

    float* outf = (float*)d_out;
    float4* out    = (float4*)outf;
    float4* mu_out = (float4*)(outf + (size_t)B * 8);
    float4* lv_out = (float4*)(outf + (size_t)B * 12);

    const int rows_per_block = 2 * NT;
    const int grid = (B + rows_per_block - 1) / rows_per_block;
    vae_kernel<<<grid, NT>>>(x, eps, w1, w21, w22, w3, w4,
                             out, mu_out, lv_out, B);
}